// round 8
// baseline (speedup 1.0000x reference)
#include <cuda_runtime.h>
#include <stdint.h>

// Problem constants (B=1024 batch, V=2 vars, M=256 latent, C=256 categories)
#define B_SZ   1024
#define M_SZ   256
#define C_SZ   256
#define NPAIR  65536          // M*M (k,m) pairs
#define CTAS   512
#define PAIRS_PER_CTA 128     // NPAIR / CTAS  (all within ONE k: k = pair>>8)
#define NITER  64             // 2 pairs per iteration
#define THREADS 256
#define NSTAGE 4
#define W1_OFF 16777216LL     // M*M*C = offset of W[1] in floats

// Scratch (static __device__ arrays: zero-initialized at load; no allocation)
__device__ float g_acc[B_SZ];   // partial sums, indexed by SLOT (team*32+lane)
__device__ int   g_xs0[B_SZ];   // x0 of sample in slot i
__device__ int   g_xs1[B_SZ];   // x1 of sample in slot i
__device__ int   g_bidx[B_SZ];  // original b of sample in slot i

// ---------------------------------------------------------------------------
// Kernel 0: bank-aware team assignment (replaces the x1 counting sort).
//   k1 reads gathers r0[x0] / r1[x1] with 32-lane warp-steps; a warp-step
//   covers one 32-slot "team". Bank conflicts depend only on x0%32 / x1%32
//   within a team. Build 32 teams of 32 samples such that within each team
//   BOTH x0%32 and x1%32 are (near-)distinct -> ~1-phase gathers on both
//   operands.
//   Method: 32 bank-classes by x0%32 (class thread owns a private team mask,
//   so the x0 axis is conflict-free by construction); the x1%32 slot of a
//   team is claimed via atomicOr on a shared mask. Unplaceable samples are
//   deferred and filled in serially (small residual conflicts).
// ---------------------------------------------------------------------------
__global__ void k0_prep(const int* __restrict__ x) {
    __shared__ int      sx0[B_SZ], sx1[B_SZ];
    __shared__ int      cls_list[B_SZ];     // sample ids grouped by x0%32 class
    __shared__ int      cls_hist[32], cls_off[32], cls_ptr[32];
    __shared__ unsigned xmask[32];          // per-team x1%32 occupancy
    __shared__ int      cnt[32];            // per-team fill count
    __shared__ int      defer_l[B_SZ];
    __shared__ int      ndefer;

    const int t = threadIdx.x;              // 0..1023

    if (t < 32) { cls_hist[t] = 0; xmask[t] = 0; cnt[t] = 0; }
    if (t == 0) ndefer = 0;
    __syncthreads();

    const int x0 = x[2 * t + 0];
    const int x1 = x[2 * t + 1];
    sx0[t] = x0; sx1[t] = x1;
    atomicAdd(&cls_hist[x0 & 31], 1);
    __syncthreads();

    if (t < 32) {   // exclusive scan of the 32-bin class histogram (one warp)
        int h = cls_hist[t], v = h;
#pragma unroll
        for (int d = 1; d < 32; d <<= 1) {
            int n = __shfl_up_sync(0xffffffffu, v, d);
            if (t >= d) v += n;
        }
        cls_off[t] = v - h;
        cls_ptr[t] = v - h;
    }
    __syncthreads();

    {   // scatter sample ids into class-grouped list
        int pos = atomicAdd(&cls_ptr[x0 & 31], 1);
        cls_list[pos] = t;
    }
    __syncthreads();

    // matching: thread c (<32) places all samples of x0-class c
    if (t < 32) {
        unsigned used = 0;                   // teams already holding my x0 bank
        const int start = cls_off[t];
        const int end   = start + cls_hist[t];
        for (int i = start; i < end; i++) {
            const int b  = cls_list[i];
            const int xb = sx1[b] & 31;
            unsigned freem = ~used;
            int placed = -1;
            int att = 0;
            while (freem && att < 12) {      // bounded first-fit over free teams
                int tt = __ffs(freem) - 1;
                freem &= freem - 1;
                unsigned old = atomicOr(&xmask[tt], 1u << xb);
                if (!(old & (1u << xb))) { placed = tt; break; }
                att++;
            }
            if (placed >= 0) {
                used |= 1u << placed;
                int lane = atomicAdd(&cnt[placed], 1);
                int slot = placed * 32 + lane;
                g_xs0[slot]  = sx0[b];
                g_xs1[slot]  = sx1[b];
                g_bidx[slot] = b;
            } else {
                defer_l[atomicAdd(&ndefer, 1)] = b;
            }
        }
    }
    __syncthreads();

    // cleanup: fill remaining slots with deferred samples (serial, small)
    if (t == 0) {
        int tt = 0;
        for (int i = 0; i < ndefer; i++) {
            int b = defer_l[i];
            while (cnt[tt] >= 32) tt++;      // exact 1024 slots total -> safe
            int slot = tt * 32 + cnt[tt];
            cnt[tt]++;
            g_xs0[slot]  = sx0[b];
            g_xs1[slot]  = sx1[b];
            g_bidx[slot] = b;
        }
    }
}

// ---------------------------------------------------------------------------
// Kernel 1: main accumulation (unchanged structure).
//   Each CTA owns 128 consecutive (k,m) pairs (one k) and ALL 1024 samples.
//   Two pairs per pipeline stage, 4-deep cp.async.cg pipeline, one
//   __syncthreads per iteration. w_sum[k] applied once in the epilogue.
//   Gathers now hit (near-)distinct banks thanks to k0's team construction.
// ---------------------------------------------------------------------------
__device__ __forceinline__ unsigned smem_u32(const void* p) {
    return (unsigned)__cvta_generic_to_shared(p);
}

__global__ void __launch_bounds__(THREADS, 4)
k1_main(const float* __restrict__ W, const float* __restrict__ w_sum) {
    // stage layout: [0:256) row0 of pair 2i, [256:512) row0 of pair 2i+1,
    //               [512:768) row1 of pair 2i, [768:1024) row1 of pair 2i+1
    __shared__ float buf[NSTAGE][4 * C_SZ];

    const int t = threadIdx.x;
    const int q0 = blockIdx.x * PAIRS_PER_CTA;
    const float wk = __ldg(w_sum + (q0 >> 8));              // k constant per CTA
    const float* base0 = W + (long long)q0 * C_SZ;          // W0 rows
    const float* base1 = W + W1_OFF + (long long)q0 * C_SZ; // W1 rows

    int ix0[4], ix1[4];
#pragma unroll
    for (int j = 0; j < 4; j++) {
        ix0[j] = g_xs0[t + 256 * j];
        ix1[j] = g_xs1[t + 256 * j];
    }
    float acc[4] = {0.f, 0.f, 0.f, 0.f};

#define ISSUE(s, it)                                                          \
    do {                                                                      \
        const float* _src = (t < 128) ? (base0 + (it) * 512 + t * 4)          \
                                      : (base1 + (it) * 512 + (t - 128) * 4); \
        unsigned _dst = smem_u32(&buf[s][(t < 128) ? (t * 4)                  \
                                                   : (512 + (t - 128) * 4)]); \
        asm volatile("cp.async.cg.shared.global [%0], [%1], 16;\n"            \
                     :: "r"(_dst), "l"(_src));                                \
    } while (0)

#pragma unroll
    for (int s = 0; s < NSTAGE - 1; s++) {
        ISSUE(s, s);
        asm volatile("cp.async.commit_group;\n");
    }

    for (int i = 0; i < NITER; i++) {
        asm volatile("cp.async.wait_group %0;\n" :: "n"(NSTAGE - 2));
        __syncthreads();   // stage i&3 visible; stage (i-1)&3 fully consumed

        const int ip = i + NSTAGE - 1;
        if (ip < NITER) ISSUE(ip & (NSTAGE - 1), ip);
        asm volatile("cp.async.commit_group;\n");

        const float* s0 = buf[i & (NSTAGE - 1)];
#pragma unroll
        for (int j = 0; j < 4; j++) {
            float a0 = s0[ix0[j]];          // distinct x0%32 -> ~1 phase
            float b0 = s0[512 + ix1[j]];    // distinct x1%32 -> ~1 phase
            float a1 = s0[256 + ix0[j]];
            float b1 = s0[768 + ix1[j]];
            acc[j] = fmaf(a0, b0, acc[j]);
            acc[j] = fmaf(a1, b1, acc[j]);
        }
    }
#undef ISSUE

#pragma unroll
    for (int j = 0; j < 4; j++)
        atomicAdd(&g_acc[t + 256 * j], acc[j] * wk);
}

// ---------------------------------------------------------------------------
// Kernel 2: out[b] = log(acc), un-permuting from slot order, and re-zero
// g_acc for the next graph replay (statics start zeroed, so the first
// correctness call and every replay all see zeroed accumulators).
// ---------------------------------------------------------------------------
__global__ void k2_final(float* __restrict__ out) {
    int i = blockIdx.x * blockDim.x + threadIdx.x;
    if (i < B_SZ) {
        out[g_bidx[i]] = logf(g_acc[i]);
        g_acc[i] = 0.0f;
    }
}

// ---------------------------------------------------------------------------
// Inputs (metadata order): d_in[0]=x int32 [1024,2], d_in[1]=W fp32 [2,256,256,256],
// d_in[2]=w_sum fp32 [256]. Output: fp32 [1024].
// ---------------------------------------------------------------------------
extern "C" void kernel_launch(void* const* d_in, const int* in_sizes, int n_in,
                              void* d_out, int out_size) {
    (void)in_sizes; (void)n_in; (void)out_size;
    const int*   x     = (const int*)d_in[0];
    const float* W     = (const float*)d_in[1];
    const float* w_sum = (const float*)d_in[2];
    float*       out   = (float*)d_out;

    k0_prep<<<1, 1024>>>(x);
    k1_main<<<CTAS, THREADS>>>(W, w_sum);
    k2_final<<<4, 256>>>(out);
}

// round 11
// speedup vs baseline: 2.0346x; 2.0346x over previous
#include <cuda_runtime.h>
#include <stdint.h>

// Problem constants (B=1024 batch, V=2 vars, M=256 latent, C=256 categories)
#define B_SZ   1024
#define M_SZ   256
#define C_SZ   256
#define NPAIR  65536          // M*M (k,m) pairs
#define CTAS   1024
#define PAIRS_PER_CTA 64      // NPAIR / CTAS  (64 aligned pairs -> single k)
#define NITER  32             // 2 pairs per iteration
#define THREADS 256
#define NSTAGE 4
#define W1_OFF 16777216LL     // M*M*C = offset of W[1] in floats

// Scratch (static __device__ arrays: no allocation, graph-capture safe)
__device__ float g_acc[B_SZ];   // partial sums, indexed in SORTED order
__device__ int   g_xs0[B_SZ];   // x0 of sorted sample i
__device__ int   g_xs1[B_SZ];   // x1 of sorted sample i (sort key)
__device__ int   g_bidx[B_SZ];  // original b of sorted sample i

// ---------------------------------------------------------------------------
// Kernel 0 (reverted to the proven R7 version): counting-sort the 1024 samples
// by x1 (consecutive sorted positions share x1 -> near-broadcast smem gathers
// in kernel 1) and zero accumulators. 1 CTA x 1024 threads; warp-shuffle scan.
// ---------------------------------------------------------------------------
__global__ void k0_prep(const int* __restrict__ x) {
    __shared__ int hist[256];
    __shared__ int wsum[8];
    __shared__ int off[256];
    const int t    = threadIdx.x;       // 0..1023
    const int lane = t & 31;

    if (t < 256) hist[t] = 0;
    __syncthreads();

    const int x0 = x[2 * t + 0];
    const int x1 = x[2 * t + 1];
    atomicAdd(&hist[x1], 1);
    g_acc[t] = 0.0f;                    // re-zero every graph replay
    __syncthreads();

    int v = 0, h = 0;
    if (t < 256) {
        h = hist[t];
        v = h;
#pragma unroll
        for (int d = 1; d < 32; d <<= 1) {
            int n = __shfl_up_sync(0xffffffffu, v, d);
            if (lane >= d) v += n;
        }
        if (lane == 31) wsum[t >> 5] = v;
    }
    __syncthreads();
    if (t == 0) {                        // serial exclusive scan of 8 warp sums
        int s = 0;
#pragma unroll
        for (int i = 0; i < 8; i++) { int tmp = wsum[i]; wsum[i] = s; s += tmp; }
    }
    __syncthreads();
    if (t < 256) off[t] = (v - h) + wsum[t >> 5];   // exclusive prefix
    __syncthreads();

    const int pos = atomicAdd(&off[x1], 1);
    g_xs0[pos]  = x0;
    g_xs1[pos]  = x1;
    g_bidx[pos] = t;
}

// ---------------------------------------------------------------------------
// Kernel 1: main accumulation.
//   1024 CTAs x 64 consecutive (k,m) pairs (one k each) x ALL 1024 samples.
//   launch_bounds(256, 8): ~6.92 CTAs/SM -> near-perfect wave balance (vs
//   3.46 with 512 CTAs where 68 SMs carried a 4th CTA), double the warps to
//   hide per-iteration wait_group+barrier latency, and ~2x aggregate
//   in-flight cp.async bytes per SM.
//   Two pairs per pipeline stage (4KB), 4-deep cp.async.cg pipeline, ONE
//   __syncthreads per iteration. w_sum[k] constant per CTA -> epilogue.
// ---------------------------------------------------------------------------
__device__ __forceinline__ unsigned smem_u32(const void* p) {
    return (unsigned)__cvta_generic_to_shared(p);
}

__global__ void __launch_bounds__(THREADS, 8)
k1_main(const float* __restrict__ W, const float* __restrict__ w_sum) {
    // stage layout: [0:256) row0 of pair 2i, [256:512) row0 of pair 2i+1,
    //               [512:768) row1 of pair 2i, [768:1024) row1 of pair 2i+1
    __shared__ float buf[NSTAGE][4 * C_SZ];

    const int t = threadIdx.x;
    const int q0 = blockIdx.x * PAIRS_PER_CTA;
    const float wk = __ldg(w_sum + (q0 >> 8));              // k constant per CTA
    const float* base0 = W + (long long)q0 * C_SZ;          // W0 rows
    const float* base1 = W + W1_OFF + (long long)q0 * C_SZ; // W1 rows

    int ix0[4], ix1[4];
#pragma unroll
    for (int j = 0; j < 4; j++) {
        ix0[j] = g_xs0[t + 256 * j];
        ix1[j] = g_xs1[t + 256 * j];
    }
    float acc[4] = {0.f, 0.f, 0.f, 0.f};

    // one 16B cp.async per thread per iteration `it` into stage `s`:
    // t<128 covers the 512-float W0 span of pairs (2it, 2it+1), t>=128 the W1 span.
#define ISSUE(s, it)                                                          \
    do {                                                                      \
        const float* _src = (t < 128) ? (base0 + (it) * 512 + t * 4)          \
                                      : (base1 + (it) * 512 + (t - 128) * 4); \
        unsigned _dst = smem_u32(&buf[s][(t < 128) ? (t * 4)                  \
                                                   : (512 + (t - 128) * 4)]); \
        asm volatile("cp.async.cg.shared.global [%0], [%1], 16;\n"            \
                     :: "r"(_dst), "l"(_src));                                \
    } while (0)

    // prologue: stages 0,1,2 for iterations 0,1,2 (3 committed groups)
#pragma unroll
    for (int s = 0; s < NSTAGE - 1; s++) {
        ISSUE(s, s);
        asm volatile("cp.async.commit_group;\n");
    }

    for (int i = 0; i < NITER; i++) {
        asm volatile("cp.async.wait_group %0;\n" :: "n"(NSTAGE - 2));
        __syncthreads();   // stage i&3 visible to all; stage (i-1)&3 consumed

        const int ip = i + NSTAGE - 1;
        if (ip < NITER) ISSUE(ip & (NSTAGE - 1), ip);
        asm volatile("cp.async.commit_group;\n");   // (possibly empty) keeps count

        const float* s0 = buf[i & (NSTAGE - 1)];
#pragma unroll
        for (int j = 0; j < 4; j++) {
            float a0 = s0[ix0[j]];          // pair A row0 (random x0)
            float b0 = s0[512 + ix1[j]];    // pair A row1 (sorted -> broadcast)
            float a1 = s0[256 + ix0[j]];    // pair B row0
            float b1 = s0[768 + ix1[j]];    // pair B row1
            acc[j] = fmaf(a0, b0, acc[j]);
            acc[j] = fmaf(a1, b1, acc[j]);
        }
    }
#undef ISSUE

#pragma unroll
    for (int j = 0; j < 4; j++)
        atomicAdd(&g_acc[t + 256 * j], acc[j] * wk);
}

// ---------------------------------------------------------------------------
// Kernel 2: out[b] = log(acc), un-permuting from sorted order.
// ---------------------------------------------------------------------------
__global__ void k2_final(float* __restrict__ out) {
    int i = blockIdx.x * blockDim.x + threadIdx.x;
    if (i < B_SZ) out[g_bidx[i]] = logf(g_acc[i]);
}

// ---------------------------------------------------------------------------
// Inputs (metadata order): d_in[0]=x int32 [1024,2], d_in[1]=W fp32 [2,256,256,256],
// d_in[2]=w_sum fp32 [256]. Output: fp32 [1024].
// ---------------------------------------------------------------------------
extern "C" void kernel_launch(void* const* d_in, const int* in_sizes, int n_in,
                              void* d_out, int out_size) {
    (void)in_sizes; (void)n_in; (void)out_size;
    const int*   x     = (const int*)d_in[0];
    const float* W     = (const float*)d_in[1];
    const float* w_sum = (const float*)d_in[2];
    float*       out   = (float*)d_out;

    k0_prep<<<1, 1024>>>(x);
    k1_main<<<CTAS, THREADS>>>(W, w_sum);
    k2_final<<<4, 256>>>(out);
}